// round 4
// baseline (speedup 1.0000x reference)
#include <cuda_runtime.h>

// Net_multi_11390253269716: 3-level GCN U-Net, 784x480 grid, C=32.
// R4: dinv pre-scaled Y (gather = pure adds), next-level gemm fused into
//     gather epilogues (11 launches total), 4-wide edge batching, fused scan.

#define NXg 784
#define NYg 480
#define C 32
#define N0 (NXg * NYg)        // 376320
#define N1 (N0 / 4)           // 94080
#define N2 (N0 / 16)          // 23520
#define E0 (4 * N0)
#define E1 (4 * N1)
#define E2 (4 * N2)
#define ETOT (E0 + E1 + E2)   // 1975680
#define M (N0 + N1 + N2)      // 493920
#define GB1 N0
#define GB2 (N0 + N1)
#define HY0 NYg               // 480
#define HY1 (NYg / 2)         // 240
#define HY2 (NYg / 4)         // 120
#define SCAN_NBLK ((M + 1023) / 1024)   // 483

typedef unsigned long long ull;

// ---------------- scratch ----------------
__device__ float4 g_Y [N0 * 8];   // ping
__device__ float4 g_Y2[N0 * 8];   // pong
__device__ float4 g_H [N0 * 8];   // GCN1 out (pre-relu), used for U0 residual
__device__ float4 g_G2[N1 * 8];   // GCN2 out (pre-relu), used for U1 residual
__device__ int   g_cnt[M];
__device__ int   g_rowptr[M + 1];
__device__ int   g_eix[ETOT];
__device__ float g_dinv[M];
__device__ int   g_bsum[SCAN_NBLK];

// ---------------- f32x2 helpers ----------------
__device__ __forceinline__ ull pk2(float a, float b) {
    ull r; asm("mov.b64 %0, {%1, %2};" : "=l"(r) : "f"(a), "f"(b)); return r;
}
__device__ __forceinline__ ull fma2_(ull a, ull b, ull c) {
    ull d; asm("fma.rn.f32x2 %0, %1, %2, %3;" : "=l"(d) : "l"(a), "l"(b), "l"(c)); return d;
}
__device__ __forceinline__ ull add2_(ull a, ull b) {
    ull d; asm("add.rn.f32x2 %0, %1, %2;" : "=l"(d) : "l"(a), "l"(b)); return d;
}
__device__ __forceinline__ float2 up2_(ull v) {
    float2 f; asm("mov.b64 {%0, %1}, %2;" : "=f"(f.x), "=f"(f.y) : "l"(v)); return f;
}
__device__ __forceinline__ float4 relu4(float4 v) {
    v.x = fmaxf(v.x, 0.f); v.y = fmaxf(v.y, 0.f);
    v.z = fmaxf(v.z, 0.f); v.w = fmaxf(v.w, 0.f);
    return v;
}

// ---------------- CSR build (5 launches) ----------------
__global__ void zero_cnt() {
    int i = blockIdx.x * blockDim.x + threadIdx.x;
    if (i < M) g_cnt[i] = 0;
}

__global__ void hist3(const int* __restrict__ d0, const int* __restrict__ d1,
                      const int* __restrict__ d2) {
    int t = blockIdx.x * blockDim.x + threadIdx.x;
    int g;
    if (t < E0) g = d0[t];
    else if (t < E0 + E1) g = GB1 + d1[t - E0];
    else if (t < ETOT) g = GB2 + d2[t - E0 - E1];
    else return;
    atomicAdd(&g_cnt[g], 1);
}

__global__ void scanA() {   // per-1024-chunk sums
    __shared__ int sb[256];
    int tid = threadIdx.x;
    int base = blockIdx.x * 1024 + tid * 4;
    int v = 0;
    #pragma unroll
    for (int k = 0; k < 4; k++) if (base + k < M) v += g_cnt[base + k];
    sb[tid] = v; __syncthreads();
    for (int off = 128; off; off >>= 1) {
        if (tid < off) sb[tid] += sb[tid + off];
        __syncthreads();
    }
    if (tid == 0) g_bsum[blockIdx.x] = sb[0];
}

// Fused scanB+scanC: each block computes its global offset by reducing the
// block-sum prefix itself, then emits rowptr / dinv / zeroed cursors.
__global__ void scanC2() {
    __shared__ int sb[256];
    __shared__ int s_pre;
    int tid = threadIdx.x;

    // prefix of block sums [0, blockIdx.x)
    int partial = 0;
    for (int j = tid; j < blockIdx.x; j += 256) partial += g_bsum[j];
    sb[tid] = partial; __syncthreads();
    for (int off = 128; off; off >>= 1) {
        if (tid < off) sb[tid] += sb[tid + off];
        __syncthreads();
    }
    if (tid == 0) s_pre = sb[0];
    __syncthreads();

    int base = blockIdx.x * 1024 + tid * 4;
    int v[4], p[4], tsum = 0;
    #pragma unroll
    for (int k = 0; k < 4; k++) {
        v[k] = (base + k < M) ? g_cnt[base + k] : 0;
        p[k] = tsum; tsum += v[k];
    }
    sb[tid] = tsum; __syncthreads();
    for (int off = 1; off < 256; off <<= 1) {
        int t = (tid >= off) ? sb[tid - off] : 0;
        __syncthreads();
        sb[tid] += t;
        __syncthreads();
    }
    int off0 = s_pre + sb[tid] - tsum;
    #pragma unroll
    for (int k = 0; k < 4; k++) {
        int i = base + k;
        if (i < M) {
            g_rowptr[i] = off0 + p[k];
            g_dinv[i] = rsqrtf((float)v[k] + 1.0f);
            g_cnt[i] = 0;
        }
    }
    if (blockIdx.x == 0 && tid == 0) g_rowptr[M] = ETOT;
}

__global__ void fill3(const int* __restrict__ ei0, const int* __restrict__ ei1,
                      const int* __restrict__ ei2) {
    int t = blockIdx.x * blockDim.x + threadIdx.x;
    int g, s;
    if (t < E0)           { g = ei0[E0 + t];                 s = ei0[t]; }
    else if (t < E0 + E1) { int e = t - E0;      g = GB1 + ei1[E1 + e]; s = ei1[e]; }
    else if (t < ETOT)    { int e = t - E0 - E1; g = GB2 + ei2[E2 + e]; s = ei2[e]; }
    else return;
    int pos = g_rowptr[g] + atomicAdd(&g_cnt[g], 1);
    g_eix[pos] = s;
}

// ---------------- shuffle gemm: row (8 thr, float4 each) @ W[32,32] --------
__device__ __forceinline__ float4 sgemm(const ulonglong2* sw, float4 xq,
                                        int sub, unsigned gm) {
    ull a01 = 0, a23 = 0;
    #pragma unroll
    for (int g = 0; g < 8; g++) {
        float x0 = __shfl_sync(gm, xq.x, g, 8);
        float x1 = __shfl_sync(gm, xq.y, g, 8);
        float x2 = __shfl_sync(gm, xq.z, g, 8);
        float x3 = __shfl_sync(gm, xq.w, g, 8);
        ulonglong2 w0 = sw[(4 * g + 0) * 8 + sub];
        ulonglong2 w1 = sw[(4 * g + 1) * 8 + sub];
        ulonglong2 w2 = sw[(4 * g + 2) * 8 + sub];
        ulonglong2 w3 = sw[(4 * g + 3) * 8 + sub];
        a01 = fma2_(pk2(x0, x0), w0.x, a01);
        a23 = fma2_(pk2(x0, x0), w0.y, a23);
        a01 = fma2_(pk2(x1, x1), w1.x, a01);
        a23 = fma2_(pk2(x1, x1), w1.y, a23);
        a01 = fma2_(pk2(x2, x2), w2.x, a01);
        a23 = fma2_(pk2(x2, x2), w2.y, a23);
        a01 = fma2_(pk2(x3, x3), w3.x, a01);
        a23 = fma2_(pk2(x3, x3), w3.y, a23);
    }
    float2 r01 = up2_(a01), r23 = up2_(a23);
    return make_float4(r01.x, r01.y, r23.x, r23.y);
}

// ---------------- gather core: row = dinv_d * (Y'[d] + sum Y'[s]) + b -------
// Y' is pre-scaled by dinv at producer side; inner loop is pure f32x2 adds.
__device__ __forceinline__ float4 gcn_row(const ulonglong2* __restrict__ Yp,
                                          int node, int sub, int gb,
                                          const float* __restrict__ bias) {
    int beg = g_rowptr[gb + node];
    int end = g_rowptr[gb + node + 1];
    ulonglong2 self = Yp[node * 8 + sub];
    ull a01 = self.x, a23 = self.y;
    int p = beg;
    for (; p + 4 <= end; p += 4) {
        int s0 = g_eix[p], s1 = g_eix[p + 1], s2 = g_eix[p + 2], s3 = g_eix[p + 3];
        ulonglong2 v0 = Yp[s0 * 8 + sub];
        ulonglong2 v1 = Yp[s1 * 8 + sub];
        ulonglong2 v2 = Yp[s2 * 8 + sub];
        ulonglong2 v3 = Yp[s3 * 8 + sub];
        a01 = add2_(add2_(a01, v0.x), add2_(v1.x, v2.x));
        a23 = add2_(add2_(a23, v0.y), add2_(v1.y, v2.y));
        a01 = add2_(a01, v3.x);
        a23 = add2_(a23, v3.y);
    }
    for (; p < end; p++) {
        int s = g_eix[p];
        ulonglong2 v = Yp[s * 8 + sub];
        a01 = add2_(a01, v.x);
        a23 = add2_(a23, v.y);
    }
    float dd = g_dinv[gb + node];
    float4 bb = ((const float4*)bias)[sub];
    float2 r01 = up2_(fma2_(a01, pk2(dd, dd), pk2(bb.x, bb.y)));
    float2 r23 = up2_(fma2_(a23, pk2(dd, dd), pk2(bb.z, bb.w)));
    return make_float4(r01.x, r01.y, r23.x, r23.y);
}

// ---------------- fc1 + gemm w1, writes Y1' = (relu(x@fc1+b)@w1)*dinv0 ------
__global__ void gemm_fc1(const float4* __restrict__ x,
                         const float* __restrict__ fc1w, const float* __restrict__ fc1b,
                         const float* __restrict__ w,
                         float4* __restrict__ Yout) {
    __shared__ ulonglong2 sw[256];
    __shared__ float4 sfw[32];
    __shared__ float4 sfb[8];
    int tid = threadIdx.x;
    sw[tid] = ((const ulonglong2*)w)[tid];
    if (tid < 32) sfw[tid] = ((const float4*)fc1w)[tid];
    if (tid < 8)  sfb[tid] = ((const float4*)fc1b)[tid];
    __syncthreads();
    int sub = tid & 7;
    unsigned gm = 0xffu << ((tid & 31) & ~7);
    int node = blockIdx.x * 32 + (tid >> 3);
    float4 r0 = sfw[0 * 8 + sub], r1 = sfw[1 * 8 + sub];
    float4 r2 = sfw[2 * 8 + sub], r3 = sfw[3 * 8 + sub];
    float4 xr = x[node];
    float4 h = sfb[sub];
    h.x += xr.x * r0.x + xr.y * r1.x + xr.z * r2.x + xr.w * r3.x;
    h.y += xr.x * r0.y + xr.y * r1.y + xr.z * r2.y + xr.w * r3.y;
    h.z += xr.x * r0.z + xr.y * r1.z + xr.z * r2.z + xr.w * r3.z;
    h.w += xr.x * r0.w + xr.y * r1.w + xr.z * r2.w + xr.w * r3.w;
    float4 y = sgemm(sw, relu4(h), sub, gm);
    float dv = g_dinv[node];
    y.x *= dv; y.y *= dv; y.z *= dv; y.w *= dv;
    Yout[node * 8 + sub] = y;
}

// ---------------- gather1: H + (even nodes) Y2' = (relu(H)@w2)*dinv1 --------
__global__ void gather_down(const float4* __restrict__ Yp,
                            const float* __restrict__ bias,
                            const float* __restrict__ wnext,
                            float4* __restrict__ OUT,   // may be null-ish: always written
                            float4* __restrict__ Yout,
                            int gb, int gbn, int hy) {
    __shared__ ulonglong2 sw[256];
    int tid = threadIdx.x;
    sw[tid] = ((const ulonglong2*)wnext)[tid];
    __syncthreads();
    int sub = tid & 7;
    unsigned gm = 0xffu << ((tid & 31) & ~7);
    int node = blockIdx.x * 32 + (tid >> 3);
    float4 row = gcn_row((const ulonglong2*)Yp, node, sub, gb, bias);
    OUT[node * 8 + sub] = row;
    int ix = node / hy, iy = node - ix * hy;
    if (((ix | iy) & 1) == 0) {
        int n1 = (ix >> 1) * (hy >> 1) + (iy >> 1);
        float4 y = sgemm(sw, relu4(row), sub, gm);
        float dv = g_dinv[gbn + n1];
        y.x *= dv; y.y *= dv; y.z *= dv; y.w *= dv;
        Yout[n1 * 8 + sub] = y;
    }
}

// ---------------- gather3/4: up-sample epilogue -----------------------------
// Computes G row (not stored), then for its 4 children c:
//   Ynext'[c] = ((relu(RES[c]) + relu(Grow)) @ wnext) * dinv[c]
__global__ void gather_up(const float4* __restrict__ Yp,
                          const float* __restrict__ bias,
                          const float4* __restrict__ RES,
                          const float* __restrict__ wnext,
                          float4* __restrict__ Yout,
                          int gb, int gbc, int hy /*coarse hy*/) {
    __shared__ ulonglong2 sw[256];
    int tid = threadIdx.x;
    sw[tid] = ((const ulonglong2*)wnext)[tid];
    __syncthreads();
    int sub = tid & 7;
    unsigned gm = 0xffu << ((tid & 31) & ~7);
    int node = blockIdx.x * 32 + (tid >> 3);
    float4 grow = relu4(gcn_row((const ulonglong2*)Yp, node, sub, gb, bias));
    int ix = node / hy, iy = node - ix * hy;
    int fhy = hy * 2;
    #pragma unroll
    for (int dx = 0; dx < 2; dx++) {
        #pragma unroll
        for (int dy = 0; dy < 2; dy++) {
            int c = (2 * ix + dx) * fhy + (2 * iy + dy);
            float4 rc = relu4(RES[c * 8 + sub]);
            float4 u = make_float4(rc.x + grow.x, rc.y + grow.y,
                                   rc.z + grow.z, rc.w + grow.w);
            float4 y = sgemm(sw, u, sub, gm);
            float dv = g_dinv[gbc + c];
            y.x *= dv; y.y *= dv; y.z *= dv; y.w *= dv;
            Yout[c * 8 + sub] = y;
        }
    }
}

// ---------------- final gather + fc2 ---------------------------------------
__global__ void gather_fc2(const float4* __restrict__ Yp,
                           const float* __restrict__ bias,
                           const float* __restrict__ w2, const float* __restrict__ b2,
                           float* __restrict__ out) {
    __shared__ float sw[96];
    int tid = threadIdx.x;
    if (tid < 96) sw[tid] = w2[tid];
    __syncthreads();
    int sub = tid & 7;
    int node = blockIdx.x * 32 + (tid >> 3);
    float4 v = relu4(gcn_row((const ulonglong2*)Yp, node, sub, 0, bias));
    int c = 4 * sub;
    float p0 = v.x * sw[(c+0)*3+0] + v.y * sw[(c+1)*3+0] + v.z * sw[(c+2)*3+0] + v.w * sw[(c+3)*3+0];
    float p1 = v.x * sw[(c+0)*3+1] + v.y * sw[(c+1)*3+1] + v.z * sw[(c+2)*3+1] + v.w * sw[(c+3)*3+1];
    float p2 = v.x * sw[(c+0)*3+2] + v.y * sw[(c+1)*3+2] + v.z * sw[(c+2)*3+2] + v.w * sw[(c+3)*3+2];
    #pragma unroll
    for (int off = 4; off; off >>= 1) {
        p0 += __shfl_down_sync(0xffffffffu, p0, off, 8);
        p1 += __shfl_down_sync(0xffffffffu, p1, off, 8);
        p2 += __shfl_down_sync(0xffffffffu, p2, off, 8);
    }
    if (sub == 0) {
        out[node * 3 + 0] = p0 + __ldg(&b2[0]);
        out[node * 3 + 1] = p1 + __ldg(&b2[1]);
        out[node * 3 + 2] = p2 + __ldg(&b2[2]);
    }
}

// ---------------------------------------------------------------------------
static inline int ceil_div(int a, int b) { return (a + b - 1) / b; }

extern "C" void kernel_launch(void* const* d_in, const int* in_sizes, int n_in,
                              void* d_out, int out_size) {
    const float* x     = (const float*)d_in[0];
    const float* fc1_w = (const float*)d_in[1];
    const float* fc1_b = (const float*)d_in[2];
    const float* w1 = (const float*)d_in[3];  const float* b1 = (const float*)d_in[4];
    const float* w2 = (const float*)d_in[5];  const float* b2 = (const float*)d_in[6];
    const float* w3 = (const float*)d_in[7];  const float* b3 = (const float*)d_in[8];
    const float* w4 = (const float*)d_in[9];  const float* b4 = (const float*)d_in[10];
    const float* w5 = (const float*)d_in[11]; const float* b5 = (const float*)d_in[12];
    const float* fc2_w = (const float*)d_in[13];
    const float* fc2_b = (const float*)d_in[14];
    const int* ei0 = (const int*)d_in[18];
    const int* ei1 = (const int*)d_in[19];
    const int* ei2 = (const int*)d_in[20];
    float* out = (float*)d_out;

    float4 *Y, *Y2b, *H, *G2;
    cudaGetSymbolAddress((void**)&Y,   g_Y);
    cudaGetSymbolAddress((void**)&Y2b, g_Y2);
    cudaGetSymbolAddress((void**)&H,   g_H);
    cudaGetSymbolAddress((void**)&G2,  g_G2);

    const int TB = 256;

    // CSR build (5 launches); also produces dinv for all levels.
    zero_cnt<<<ceil_div(M, TB), TB>>>();
    hist3<<<ceil_div(ETOT, TB), TB>>>(ei0 + E0, ei1 + E1, ei2 + E2);
    scanA<<<SCAN_NBLK, 256>>>();
    scanC2<<<SCAN_NBLK, 256>>>();
    fill3<<<ceil_div(ETOT, TB), TB>>>(ei0, ei1, ei2);

    // Y1' = (relu(x@fc1+b)@w1)*dinv0           [g_Y]
    gemm_fc1<<<N0 / 32, TB>>>((const float4*)x, fc1_w, fc1_b, w1, Y);

    // gather1: H = A0(Y1')+b1 ; even nodes -> Y2' = (relu(H)@w2)*dinv1  [g_Y2]
    gather_down<<<N0 / 32, TB>>>(Y, b1, w2, H, Y2b, 0, GB1, HY0);

    // gather2: G2 = A1(Y2')+b2 ; even nodes -> Y3' = (relu(G2)@w3)*dinv2 [g_Y]
    gather_down<<<N1 / 32, TB>>>(Y2b, b2, w3, G2, Y, GB1, GB2, HY1);

    // gather3: G3 row = A2(Y3')+b3 ; children -> Y4' = ((relu(G2)+relu(G3))@w4)*dinv1 [g_Y2]
    gather_up<<<N2 / 32, TB>>>(Y, b3, G2, w4, Y2b, GB2, GB1, HY2);

    // gather4: G4 row = A1(Y4')+b4 ; children -> Y5' = ((relu(H)+relu(G4))@w5)*dinv0 [g_Y]
    gather_up<<<N1 / 32, TB>>>(Y2b, b4, H, w5, Y, GB1, 0, HY1);

    // gather5 + fc2
    gather_fc2<<<N0 / 32, TB>>>(Y, b5, fc2_w, fc2_b, out);

    (void)in_sizes; (void)n_in; (void)out_size;
}

// round 5
// speedup vs baseline: 1.3825x; 1.3825x over previous
#include <cuda_runtime.h>

// Net_multi_11390253269716: 3-level GCN U-Net, 784x480 grid, C=32.
// R5: R3 pipeline (separate gemm/gather) + dinv-prescaled Y (pure-add gather),
//     4-wide edge batching, 5-launch CSR build.

#define NXg 784
#define NYg 480
#define C 32
#define N0 (NXg * NYg)        // 376320
#define N1 (N0 / 4)           // 94080
#define N2 (N0 / 16)          // 23520
#define E0 (4 * N0)
#define E1 (4 * N1)
#define E2 (4 * N2)
#define ETOT (E0 + E1 + E2)   // 1975680
#define M (N0 + N1 + N2)      // 493920
#define GB1 N0
#define GB2 (N0 + N1)
#define SCAN_NBLK ((M + 1023) / 1024)   // 483

typedef unsigned long long ull;

// ---------------- scratch ----------------
__device__ float4 g_Y [N0 * 8];   // pre-scaled x@w temp (levels reuse prefix)
__device__ float4 g_H [N0 * 8];   // GCN1 out (pre-relu)
__device__ float4 g_G2[N1 * 8];
__device__ float4 g_G4[N1 * 8];
__device__ float4 g_G3[N2 * 8];
__device__ int   g_cnt[M];
__device__ int   g_rowptr[M + 1];
__device__ int   g_eix[ETOT];
__device__ float g_dinv[M];
__device__ int   g_bsum[SCAN_NBLK];

// ---------------- f32x2 helpers ----------------
__device__ __forceinline__ ull pk2(float a, float b) {
    ull r; asm("mov.b64 %0, {%1, %2};" : "=l"(r) : "f"(a), "f"(b)); return r;
}
__device__ __forceinline__ ull fma2_(ull a, ull b, ull c) {
    ull d; asm("fma.rn.f32x2 %0, %1, %2, %3;" : "=l"(d) : "l"(a), "l"(b), "l"(c)); return d;
}
__device__ __forceinline__ ull add2_(ull a, ull b) {
    ull d; asm("add.rn.f32x2 %0, %1, %2;" : "=l"(d) : "l"(a), "l"(b)); return d;
}
__device__ __forceinline__ float2 up2_(ull v) {
    float2 f; asm("mov.b64 {%0, %1}, %2;" : "=f"(f.x), "=f"(f.y) : "l"(v)); return f;
}
__device__ __forceinline__ float4 relu4(float4 v) {
    v.x = fmaxf(v.x, 0.f); v.y = fmaxf(v.y, 0.f);
    v.z = fmaxf(v.z, 0.f); v.w = fmaxf(v.w, 0.f);
    return v;
}

// ---------------- CSR build (5 launches) ----------------
__global__ void zero_cnt() {
    int i = blockIdx.x * blockDim.x + threadIdx.x;
    if (i < M) g_cnt[i] = 0;
}

__global__ void hist3(const int* __restrict__ d0, const int* __restrict__ d1,
                      const int* __restrict__ d2) {
    int t = blockIdx.x * blockDim.x + threadIdx.x;
    int g;
    if (t < E0) g = d0[t];
    else if (t < E0 + E1) g = GB1 + d1[t - E0];
    else if (t < ETOT) g = GB2 + d2[t - E0 - E1];
    else return;
    atomicAdd(&g_cnt[g], 1);
}

__global__ void scanA() {   // per-1024-chunk sums
    __shared__ int sb[256];
    int tid = threadIdx.x;
    int base = blockIdx.x * 1024 + tid * 4;
    int v = 0;
    #pragma unroll
    for (int k = 0; k < 4; k++) if (base + k < M) v += g_cnt[base + k];
    sb[tid] = v; __syncthreads();
    for (int off = 128; off; off >>= 1) {
        if (tid < off) sb[tid] += sb[tid + off];
        __syncthreads();
    }
    if (tid == 0) g_bsum[blockIdx.x] = sb[0];
}

// Fused scanB+scanC: each block reduces its prefix of block sums, then emits
// rowptr / dinv / zeroed cursors.
__global__ void scanC2() {
    __shared__ int sb[256];
    __shared__ int s_pre;
    int tid = threadIdx.x;
    int partial = 0;
    for (int j = tid; j < blockIdx.x; j += 256) partial += g_bsum[j];
    sb[tid] = partial; __syncthreads();
    for (int off = 128; off; off >>= 1) {
        if (tid < off) sb[tid] += sb[tid + off];
        __syncthreads();
    }
    if (tid == 0) s_pre = sb[0];
    __syncthreads();

    int base = blockIdx.x * 1024 + tid * 4;
    int v[4], p[4], tsum = 0;
    #pragma unroll
    for (int k = 0; k < 4; k++) {
        v[k] = (base + k < M) ? g_cnt[base + k] : 0;
        p[k] = tsum; tsum += v[k];
    }
    sb[tid] = tsum; __syncthreads();
    for (int off = 1; off < 256; off <<= 1) {
        int t = (tid >= off) ? sb[tid - off] : 0;
        __syncthreads();
        sb[tid] += t;
        __syncthreads();
    }
    int off0 = s_pre + sb[tid] - tsum;
    #pragma unroll
    for (int k = 0; k < 4; k++) {
        int i = base + k;
        if (i < M) {
            g_rowptr[i] = off0 + p[k];
            g_dinv[i] = rsqrtf((float)v[k] + 1.0f);
            g_cnt[i] = 0;
        }
    }
    if (blockIdx.x == 0 && tid == 0) g_rowptr[M] = ETOT;
}

__global__ void fill3(const int* __restrict__ ei0, const int* __restrict__ ei1,
                      const int* __restrict__ ei2) {
    int t = blockIdx.x * blockDim.x + threadIdx.x;
    int g, s;
    if (t < E0)           { g = ei0[E0 + t];                 s = ei0[t]; }
    else if (t < E0 + E1) { int e = t - E0;      g = GB1 + ei1[E1 + e]; s = ei1[e]; }
    else if (t < ETOT)    { int e = t - E0 - E1; g = GB2 + ei2[E2 + e]; s = ei2[e]; }
    else return;
    int pos = g_rowptr[g] + atomicAdd(&g_cnt[g], 1);
    g_eix[pos] = s;
}

// ---------------- gemm: 8 thr/node, 4 nodes/group, f32x2, prescaled out -----
#define GEMM_PROLOG(n_)                                                   \
    __shared__ ulonglong2 swu[256];                                       \
    int tid = threadIdx.x;                                                \
    swu[tid] = ((const ulonglong2*)w)[tid];                               \
    int sub = tid & 7;                                                    \
    int nb = (blockIdx.x * 32 + (tid >> 3)) * 4;                          \
    float4 xq[4];

#define GEMM_BODY(n_, gb_)                                                \
    __syncthreads();                                                      \
    ull a01[4] = {0, 0, 0, 0}, a23[4] = {0, 0, 0, 0};                     \
    _Pragma("unroll")                                                     \
    for (int g = 0; g < 8; g++) {                                         \
        ulonglong2 w0 = swu[(4 * g + 0) * 8 + sub];                       \
        ulonglong2 w1 = swu[(4 * g + 1) * 8 + sub];                       \
        ulonglong2 w2 = swu[(4 * g + 2) * 8 + sub];                       \
        ulonglong2 w3 = swu[(4 * g + 3) * 8 + sub];                       \
        _Pragma("unroll")                                                 \
        for (int j = 0; j < 4; j++) {                                     \
            float x0 = __shfl_sync(0xffffffffu, xq[j].x, g, 8);           \
            float x1 = __shfl_sync(0xffffffffu, xq[j].y, g, 8);           \
            float x2 = __shfl_sync(0xffffffffu, xq[j].z, g, 8);           \
            float x3 = __shfl_sync(0xffffffffu, xq[j].w, g, 8);           \
            a01[j] = fma2_(pk2(x0, x0), w0.x, a01[j]);                    \
            a23[j] = fma2_(pk2(x0, x0), w0.y, a23[j]);                    \
            a01[j] = fma2_(pk2(x1, x1), w1.x, a01[j]);                    \
            a23[j] = fma2_(pk2(x1, x1), w1.y, a23[j]);                    \
            a01[j] = fma2_(pk2(x2, x2), w2.x, a01[j]);                    \
            a23[j] = fma2_(pk2(x2, x2), w2.y, a23[j]);                    \
            a01[j] = fma2_(pk2(x3, x3), w3.x, a01[j]);                    \
            a23[j] = fma2_(pk2(x3, x3), w3.y, a23[j]);                    \
        }                                                                 \
    }                                                                     \
    _Pragma("unroll")                                                     \
    for (int j = 0; j < 4; j++)                                           \
        if (nb + j < n_) {                                                \
            float dv = g_dinv[(gb_) + nb + j];                            \
            ull dd = pk2(dv, dv);                                         \
            ulonglong2 r;                                                 \
            r.x = fma2_(a01[j], dd, 0ull);                                \
            r.y = fma2_(a23[j], dd, 0ull);                                \
            ((ulonglong2*)Y)[(nb + j) * 8 + sub] = r;                     \
        }

// fc1 fused: xq = relu(x @ fc1_w + fc1_b)
__global__ void gemm_fc1(const float4* __restrict__ x,
                         const float* __restrict__ fc1w, const float* __restrict__ fc1b,
                         const float* __restrict__ w,
                         float4* __restrict__ Y, int n)
{
    GEMM_PROLOG(n)
    __shared__ float4 sfw[32];
    __shared__ float4 sfb[8];
    if (tid < 32) sfw[tid] = ((const float4*)fc1w)[tid];
    if (tid < 8)  sfb[tid] = ((const float4*)fc1b)[tid];
    __syncthreads();
    float4 r0 = sfw[0 * 8 + sub], r1 = sfw[1 * 8 + sub];
    float4 r2 = sfw[2 * 8 + sub], r3 = sfw[3 * 8 + sub];
    float4 bb = sfb[sub];
    #pragma unroll
    for (int j = 0; j < 4; j++) {
        float4 xr = (nb + j < n) ? x[nb + j] : make_float4(0.f, 0.f, 0.f, 0.f);
        float4 h = bb;
        h.x += xr.x * r0.x + xr.y * r1.x + xr.z * r2.x + xr.w * r3.x;
        h.y += xr.x * r0.y + xr.y * r1.y + xr.z * r2.y + xr.w * r3.y;
        h.z += xr.x * r0.z + xr.y * r1.z + xr.z * r2.z + xr.w * r3.z;
        h.w += xr.x * r0.w + xr.y * r1.w + xr.z * r2.w + xr.w * r3.w;
        xq[j] = relu4(h);
    }
    GEMM_BODY(n, 0)
}

// downsample fused: xq = relu(in[(2ix)*win + 2iy])
__global__ void gemm_down(const float4* __restrict__ in,
                          const float* __restrict__ w,
                          float4* __restrict__ Y, int n, int hy, int win, int gb)
{
    GEMM_PROLOG(n)
    #pragma unroll
    for (int j = 0; j < 4; j++) {
        int node = nb + j;
        if (node < n) {
            int ix = node / hy, iy = node - ix * hy;
            int sn = (2 * ix) * win + 2 * iy;
            xq[j] = relu4(in[sn * 8 + sub]);
        } else xq[j] = make_float4(0.f, 0.f, 0.f, 0.f);
    }
    GEMM_BODY(n, gb)
}

// upsample+residual fused
__global__ void gemm_upadd(const float4* __restrict__ base,
                           const float4* __restrict__ coarse,
                           const float* __restrict__ w,
                           float4* __restrict__ Y, int n, int hy, int gb)
{
    GEMM_PROLOG(n)
    #pragma unroll
    for (int j = 0; j < 4; j++) {
        int node = nb + j;
        if (node < n) {
            int ix = node / hy, iy = node - ix * hy;
            int cn = (ix >> 1) * (hy >> 1) + (iy >> 1);
            float4 xb = relu4(base[node * 8 + sub]);
            float4 xc = relu4(coarse[cn * 8 + sub]);
            xq[j] = make_float4(xb.x + xc.x, xb.y + xc.y, xb.z + xc.z, xb.w + xc.w);
        } else xq[j] = make_float4(0.f, 0.f, 0.f, 0.f);
    }
    GEMM_BODY(n, gb)
}

// ---------------- gather: row = dinv_d*(Y'[d] + sum Y'[s]) + b --------------
__device__ __forceinline__ float4 gcn_row(const ulonglong2* __restrict__ Yp,
                                          int node, int sub, int gb,
                                          const float* __restrict__ bias) {
    int beg = g_rowptr[gb + node];
    int end = g_rowptr[gb + node + 1];
    ulonglong2 self = Yp[node * 8 + sub];
    ull a01 = self.x, a23 = self.y;
    int p = beg;
    for (; p + 4 <= end; p += 4) {
        int s0 = g_eix[p], s1 = g_eix[p + 1], s2 = g_eix[p + 2], s3 = g_eix[p + 3];
        ulonglong2 v0 = Yp[s0 * 8 + sub];
        ulonglong2 v1 = Yp[s1 * 8 + sub];
        ulonglong2 v2 = Yp[s2 * 8 + sub];
        ulonglong2 v3 = Yp[s3 * 8 + sub];
        a01 = add2_(add2_(a01, v0.x), add2_(v1.x, v2.x));
        a23 = add2_(add2_(a23, v0.y), add2_(v1.y, v2.y));
        a01 = add2_(a01, v3.x);
        a23 = add2_(a23, v3.y);
    }
    for (; p < end; p++) {
        int s = g_eix[p];
        ulonglong2 v = Yp[s * 8 + sub];
        a01 = add2_(a01, v.x);
        a23 = add2_(a23, v.y);
    }
    float dd = g_dinv[gb + node];
    float4 bb = ((const float4*)bias)[sub];
    float2 r01 = up2_(fma2_(a01, pk2(dd, dd), pk2(bb.x, bb.y)));
    float2 r23 = up2_(fma2_(a23, pk2(dd, dd), pk2(bb.z, bb.w)));
    return make_float4(r01.x, r01.y, r23.x, r23.y);
}

__global__ void gather(const float4* __restrict__ Yf,
                       const float* __restrict__ bias,
                       float4* __restrict__ OUT, int n, int gb)
{
    int t = blockIdx.x * blockDim.x + threadIdx.x;
    int node = t >> 3, sub = t & 7;
    if (node >= n) return;
    OUT[node * 8 + sub] = gcn_row((const ulonglong2*)Yf, node, sub, gb, bias);
}

// final gather with fc2 epilogue
__global__ void gather_fc2(const float4* __restrict__ Yf,
                           const float* __restrict__ bias,
                           const float* __restrict__ w2, const float* __restrict__ b2,
                           float* __restrict__ out, int n)
{
    __shared__ float sw[96];
    int tid = threadIdx.x;
    if (tid < 96) sw[tid] = w2[tid];
    __syncthreads();
    int t = blockIdx.x * blockDim.x + tid;
    int node = t >> 3, sub = t & 7;
    if (node >= n) return;
    float4 v = relu4(gcn_row((const ulonglong2*)Yf, node, sub, 0, bias));
    int c = 4 * sub;
    float p0 = v.x * sw[(c+0)*3+0] + v.y * sw[(c+1)*3+0] + v.z * sw[(c+2)*3+0] + v.w * sw[(c+3)*3+0];
    float p1 = v.x * sw[(c+0)*3+1] + v.y * sw[(c+1)*3+1] + v.z * sw[(c+2)*3+1] + v.w * sw[(c+3)*3+1];
    float p2 = v.x * sw[(c+0)*3+2] + v.y * sw[(c+1)*3+2] + v.z * sw[(c+2)*3+2] + v.w * sw[(c+3)*3+2];
    #pragma unroll
    for (int off = 4; off; off >>= 1) {
        p0 += __shfl_down_sync(0xffffffffu, p0, off, 8);
        p1 += __shfl_down_sync(0xffffffffu, p1, off, 8);
        p2 += __shfl_down_sync(0xffffffffu, p2, off, 8);
    }
    if (sub == 0) {
        out[node * 3 + 0] = p0 + __ldg(&b2[0]);
        out[node * 3 + 1] = p1 + __ldg(&b2[1]);
        out[node * 3 + 2] = p2 + __ldg(&b2[2]);
    }
}

// ---------------------------------------------------------------------------
static inline int ceil_div(int a, int b) { return (a + b - 1) / b; }

extern "C" void kernel_launch(void* const* d_in, const int* in_sizes, int n_in,
                              void* d_out, int out_size) {
    const float* x     = (const float*)d_in[0];
    const float* fc1_w = (const float*)d_in[1];
    const float* fc1_b = (const float*)d_in[2];
    const float* w1 = (const float*)d_in[3];  const float* b1 = (const float*)d_in[4];
    const float* w2 = (const float*)d_in[5];  const float* b2 = (const float*)d_in[6];
    const float* w3 = (const float*)d_in[7];  const float* b3 = (const float*)d_in[8];
    const float* w4 = (const float*)d_in[9];  const float* b4 = (const float*)d_in[10];
    const float* w5 = (const float*)d_in[11]; const float* b5 = (const float*)d_in[12];
    const float* fc2_w = (const float*)d_in[13];
    const float* fc2_b = (const float*)d_in[14];
    const int* ei0 = (const int*)d_in[18];
    const int* ei1 = (const int*)d_in[19];
    const int* ei2 = (const int*)d_in[20];
    float* out = (float*)d_out;

    float4 *Y, *H, *G2, *G4, *G3;
    cudaGetSymbolAddress((void**)&Y,  g_Y);
    cudaGetSymbolAddress((void**)&H,  g_H);
    cudaGetSymbolAddress((void**)&G2, g_G2);
    cudaGetSymbolAddress((void**)&G4, g_G4);
    cudaGetSymbolAddress((void**)&G3, g_G3);

    const int TB = 256;

    // CSR build (also produces dinv for all levels)
    zero_cnt<<<ceil_div(M, TB), TB>>>();
    hist3<<<ceil_div(ETOT, TB), TB>>>(ei0 + E0, ei1 + E1, ei2 + E2);
    scanA<<<SCAN_NBLK, 256>>>();
    scanC2<<<SCAN_NBLK, 256>>>();
    fill3<<<ceil_div(ETOT, TB), TB>>>(ei0, ei1, ei2);

    // GCN1 (level 0), fc1 fused; Y prescaled by dinv0
    gemm_fc1<<<ceil_div(N0, 128), TB>>>((const float4*)x, fc1_w, fc1_b, w1, Y, N0);
    gather<<<N0 / 32, TB>>>(Y, b1, H, N0, 0);

    // GCN2 (level 1)
    gemm_down<<<ceil_div(N1, 128), TB>>>(H, w2, Y, N1, NYg / 2, NYg, GB1);
    gather<<<N1 / 32, TB>>>(Y, b2, G2, N1, GB1);

    // GCN3 (level 2)
    gemm_down<<<ceil_div(N2, 128), TB>>>(G2, w3, Y, N2, NYg / 4, NYg / 2, GB2);
    gather<<<N2 / 32, TB>>>(Y, b3, G3, N2, GB2);

    // GCN4 (level 1)
    gemm_upadd<<<ceil_div(N1, 128), TB>>>(G2, G3, w4, Y, N1, NYg / 2, GB1);
    gather<<<N1 / 32, TB>>>(Y, b4, G4, N1, GB1);

    // GCN5 (level 0) + fc2 fused into gather
    gemm_upadd<<<ceil_div(N0, 128), TB>>>(H, G4, w5, Y, N0, NYg, 0);
    gather_fc2<<<N0 / 32, TB>>>(Y, b5, fc2_w, fc2_b, out, N0);

    (void)in_sizes; (void)n_in; (void)out_size;
}